// round 1
// baseline (speedup 1.0000x reference)
#include <cuda_runtime.h>
#include <cuda_bf16.h>

// Problem: M=3, L=16, BATCH=2e6.
// y[b] = sum_{s=0}^{21} w[s] * res_s where res_s picks the largest-m valid
// candidate (l = s - 3m in [0,15]) whose cond is true; val = 0.5*cos(x_m - phi_{m,l}) + 0.5.
// Output layout: d_out[0..B) = y, d_out[B..B+48) = weight (reference returns (y, weight)).

#define M_DIM 3
#define L_DIM 16
#define NSEG 22   // segments 22..47 have no candidates -> contribute 0

// Precomputed per-entry constants: (phi, 0.5*cos(phi), 0.5*sin(phi), interval[m])
__device__ float4 g_entry[M_DIM * L_DIM];

__global__ void setup_kernel(const float* __restrict__ phis,
                             const float* __restrict__ interval) {
    int e = threadIdx.x;
    if (e < M_DIM * L_DIM) {
        int m = e / L_DIM;
        float phi = phis[e];
        float s, c;
        sincosf(phi, &s, &c);          // accurate; runs once, 48 threads
        float4 v;
        v.x = phi;
        v.y = 0.5f * c;
        v.z = 0.5f * s;
        v.w = interval[m];
        g_entry[e] = v;
    }
}

__global__ void __launch_bounds__(256) main_kernel(const float* __restrict__ x,
                                                   const float* __restrict__ w,
                                                   float* __restrict__ out,
                                                   int B) {
    __shared__ float4 sE[M_DIM * L_DIM];
    __shared__ float  sW[NSEG];

    int t = threadIdx.x;
    if (t < M_DIM * L_DIM) sE[t] = g_entry[t];
    if (t < NSEG)          sW[t] = w[t];
    __syncthreads();

    int i = blockIdx.x * blockDim.x + t;
    if (i >= B) return;

    // x is (B, 3) row-major
    float x0 = x[3 * i + 0];
    float x1 = x[3 * i + 1];
    float x2 = x[3 * i + 2];

    float s0, c0, s1, c1, s2, c2;
    __sincosf(x0, &s0, &c0);
    __sincosf(x1, &s1, &c1);
    __sincosf(x2, &s2, &c2);

    float xm[M_DIM] = {x0, x1, x2};
    float cm[M_DIM] = {c0, c1, c2};
    float sm[M_DIM] = {s0, s1, s2};

    float acc = 0.0f;
    #pragma unroll
    for (int s = 0; s < NSEG; s++) {
        float r = 0.0f;
        #pragma unroll
        for (int m = 0; m < M_DIM; m++) {
            int l = s - 3 * m;                 // compile-time after unroll
            if (l < 0 || l >= L_DIM) continue;
            float4 e = sE[m * L_DIM + l];
            // cond computed EXACTLY as the reference: d = x - phi; d > -iv && d <= iv
            float d = xm[m] - e.x;
            bool cond = (d > -e.w) && (d <= e.w);
            // val = cos(x)*0.5cos(phi) + sin(x)*0.5sin(phi) + 0.5
            float val = fmaf(cm[m], e.y, fmaf(sm[m], e.z, 0.5f));
            r = cond ? val : r;                // later (larger) m overrides: segment_max winner
        }
        acc = fmaf(sW[s], r, acc);
    }

    out[i] = acc;
    if (i < M_DIM * L_DIM) out[B + i] = w[i];  // echo weight (second tuple output)
}

extern "C" void kernel_launch(void* const* d_in, const int* in_sizes, int n_in,
                              void* d_out, int out_size) {
    const float* x        = (const float*)d_in[0];   // (B, 3)
    const float* phis     = (const float*)d_in[1];   // (3, 16)
    const float* interval = (const float*)d_in[2];   // (3,)
    const float* weight   = (const float*)d_in[3];   // (48,)
    float* out = (float*)d_out;

    int B = in_sizes[0] / M_DIM;

    setup_kernel<<<1, 64>>>(phis, interval);
    int threads = 256;
    int blocks = (B + threads - 1) / threads;
    main_kernel<<<blocks, threads>>>(x, weight, out, B);
}